// round 1
// baseline (speedup 1.0000x reference)
#include <cuda_runtime.h>
#include <math.h>

#define V 50257
#define H 1024
#define L 128

// ---------------- scratch (device globals; no allocations allowed) ----------
__device__ float g_attn_logits[L];
__device__ float g_attn_weights[L];
__device__ float g_attn_applied[H];
__device__ float g_x[H];
__device__ float g_gi[3 * H];
__device__ float g_gh[3 * H];
__device__ float g_h0[H];
__device__ float g_h1[H];
__device__ float g_red_max[128];
__device__ float g_red_sum[128];
__device__ float g_logZ;

// ---------------- reduction helpers ----------------
__inline__ __device__ float warpReduceSum(float v) {
    #pragma unroll
    for (int o = 16; o > 0; o >>= 1) v += __shfl_down_sync(0xffffffffu, v, o);
    return v;
}
__inline__ __device__ float warpReduceMax(float v) {
    #pragma unroll
    for (int o = 16; o > 0; o >>= 1) v = fmaxf(v, __shfl_down_sync(0xffffffffu, v, o));
    return v;
}
// block reduce sum into thread 0 (blockDim.x <= 1024, multiple of 32)
__inline__ __device__ float blockReduceSum(float v, float* sh) {
    int lane = threadIdx.x & 31, wid = threadIdx.x >> 5;
    v = warpReduceSum(v);
    if (lane == 0) sh[wid] = v;
    __syncthreads();
    int nw = blockDim.x >> 5;
    v = (threadIdx.x < nw) ? sh[lane] : 0.f;
    if (wid == 0) v = warpReduceSum(v);
    return v;
}
__inline__ __device__ float blockReduceMax(float v, float* sh) {
    int lane = threadIdx.x & 31, wid = threadIdx.x >> 5;
    v = warpReduceMax(v);
    if (lane == 0) sh[wid] = v;
    __syncthreads();
    int nw = blockDim.x >> 5;
    v = (threadIdx.x < nw) ? sh[lane] : -INFINITY;
    if (wid == 0) v = warpReduceMax(v);
    return v;
}

// ---------------- K1: attention logits --------------------------------------
// one block per l (128 blocks, 256 threads); dot of length 2H over [embedded, hidden0]
__global__ void k_attn_logits(const long long* __restrict__ ids,
                              const float* __restrict__ emb,
                              const float* __restrict__ hidden,
                              const float* __restrict__ attn_w,
                              const float* __restrict__ attn_b) {
    __shared__ float sh[32];
    int l = blockIdx.x;
    const float* emb_row = emb + (size_t)ids[0] * H;
    const float* wrow = attn_w + (size_t)l * (2 * H);
    float s = 0.f;
    for (int k = threadIdx.x; k < 2 * H; k += blockDim.x) {
        float in = (k < H) ? emb_row[k] : hidden[k - H];
        s += wrow[k] * in;
    }
    s = blockReduceSum(s, sh);
    if (threadIdx.x == 0) g_attn_logits[l] = s + attn_b[l];
}

// ---------------- K2: softmax over 128 --------------------------------------
__global__ void k_attn_softmax(float* __restrict__ out /* d_out */) {
    __shared__ float sh[32];
    __shared__ float sM, sS;
    int t = threadIdx.x;  // 128 threads
    float v = g_attn_logits[t];
    float m = blockReduceMax(v, sh);
    if (t == 0) sM = m;
    __syncthreads();
    float e = expf(v - sM);
    __syncthreads();
    float s = blockReduceSum(e, sh);
    if (t == 0) sS = s;
    __syncthreads();
    float w = e / sS;
    g_attn_weights[t] = w;
    out[V + 2 * H + t] = w;   // attn_weights output
}

// ---------------- K3: attn_applied = aw @ encoder_outputs -------------------
// grid 8 x 128 threads, one h per thread
__global__ void k_attn_applied(const float* __restrict__ enc) {
    __shared__ float aw[L];
    int t = threadIdx.x;
    aw[t] = g_attn_weights[t];
    __syncthreads();
    int h = blockIdx.x * blockDim.x + t;
    float s = 0.f;
    #pragma unroll 8
    for (int l = 0; l < L; l++) s += aw[l] * enc[(size_t)l * H + h];
    g_attn_applied[h] = s;
}

// ---------------- K4: comb + relu -> x ---------------------------------------
// one block per output (1024 blocks, 256 threads), dot length 2H
__global__ void k_comb(const long long* __restrict__ ids,
                       const float* __restrict__ emb,
                       const float* __restrict__ comb_w,
                       const float* __restrict__ comb_b) {
    __shared__ float sh[32];
    int j = blockIdx.x;
    const float* emb_row = emb + (size_t)ids[0] * H;
    const float* wrow = comb_w + (size_t)j * (2 * H);
    float s = 0.f;
    for (int k = threadIdx.x; k < 2 * H; k += blockDim.x) {
        float in = (k < H) ? emb_row[k] : g_attn_applied[k - H];
        s += wrow[k] * in;
    }
    s = blockReduceSum(s, sh);
    if (threadIdx.x == 0) {
        float r = s + comb_b[j];
        g_x[j] = r > 0.f ? r : 0.f;
    }
}

// ---------------- K5/K7: GRU gates (gi, gh) ----------------------------------
// one block per gate row j (3072 blocks, 256 threads); fully vectorized float4
__global__ void k_gru_gates(const float* __restrict__ xin,
                            const float* __restrict__ hprev,
                            const float* __restrict__ w_ih,
                            const float* __restrict__ w_hh,
                            const float* __restrict__ b_ih,
                            const float* __restrict__ b_hh) {
    __shared__ float sha[32];
    __shared__ float shb[32];
    int j = blockIdx.x;
    int t = threadIdx.x;  // 256 threads, each one float4 (256*4 = 1024)
    const float4* wi = (const float4*)(w_ih + (size_t)j * H);
    const float4* wh = (const float4*)(w_hh + (size_t)j * H);
    const float4* xv4 = (const float4*)xin;
    const float4* hv4 = (const float4*)hprev;
    float4 wiv = wi[t], whv = wh[t], xv = xv4[t], hv = hv4[t];
    float a = wiv.x * xv.x + wiv.y * xv.y + wiv.z * xv.z + wiv.w * xv.w;
    float b = whv.x * hv.x + whv.y * hv.y + whv.z * hv.z + whv.w * hv.w;
    a = blockReduceSum(a, sha);
    __syncthreads();
    b = blockReduceSum(b, shb);
    if (t == 0) {
        g_gi[j] = a + b_ih[j];
        g_gh[j] = b + b_hh[j];
    }
}

// ---------------- K6/K8: GRU combine ------------------------------------------
// 1 block, 1024 threads
__global__ void k_gru_combine(const float* __restrict__ hprev,
                              float* __restrict__ hnew,       // scratch
                              float* __restrict__ out_hid) {  // d_out slot
    int t = threadIdx.x;
    float r = 1.f / (1.f + expf(-(g_gi[t] + g_gh[t])));
    float z = 1.f / (1.f + expf(-(g_gi[H + t] + g_gh[H + t])));
    float n = tanhf(g_gi[2 * H + t] + r * g_gh[2 * H + t]);
    float h = (1.f - z) * n + z * hprev[t];
    hnew[t] = h;
    out_hid[t] = h;
}

// ---------------- K9: logits = h1 @ out_w^T + b -------------------------------
// one warp per output row; 8 warps/block
__global__ void k_logits(const float* __restrict__ out_w,
                         const float* __restrict__ out_b,
                         float* __restrict__ logits) {
    int warp = threadIdx.x >> 5;
    int lane = threadIdx.x & 31;
    int j = blockIdx.x * 8 + warp;
    if (j >= V) return;
    const float4* w = (const float4*)(out_w + (size_t)j * H);
    const float4* h = (const float4*)g_h1;
    float s = 0.f;
    #pragma unroll
    for (int i = 0; i < 8; i++) {
        int idx = i * 32 + lane;          // 256 float4 per row
        float4 wv = w[idx];
        float4 hv = h[idx];
        s += wv.x * hv.x + wv.y * hv.y + wv.z * hv.z + wv.w * hv.w;
    }
    s = warpReduceSum(s);
    if (lane == 0) logits[j] = s + out_b[j];
}

// ---------------- K10: per-block max/sumexp partials ---------------------------
#define RED_BLOCKS 128
__global__ void k_lse_partial(const float* __restrict__ logits) {
    __shared__ float sh[32];
    __shared__ float sM;
    const int chunk = (V + RED_BLOCKS - 1) / RED_BLOCKS;  // 393
    int start = blockIdx.x * chunk;
    int end = min(start + chunk, V);
    float m = -INFINITY;
    for (int i = start + threadIdx.x; i < end; i += blockDim.x)
        m = fmaxf(m, logits[i]);
    m = blockReduceMax(m, sh);
    if (threadIdx.x == 0) sM = m;
    __syncthreads();
    float M = sM;
    float s = 0.f;
    for (int i = start + threadIdx.x; i < end; i += blockDim.x)
        s += expf(logits[i] - M);
    __syncthreads();
    s = blockReduceSum(s, sh);
    if (threadIdx.x == 0) {
        g_red_max[blockIdx.x] = M;
        g_red_sum[blockIdx.x] = s;
    }
}

// ---------------- K11: combine partials -> logZ --------------------------------
__global__ void k_lse_final() {
    __shared__ float sh[32];
    __shared__ float sM;
    int t = threadIdx.x;  // 128
    float m = g_red_max[t];
    float M = blockReduceMax(m, sh);
    if (t == 0) sM = M;
    __syncthreads();
    M = sM;
    float s = g_red_sum[t] * expf(g_red_max[t] - M);
    __syncthreads();
    s = blockReduceSum(s, sh);
    if (t == 0) g_logZ = M + logf(s);
}

// ---------------- K12: apply log_softmax in place -------------------------------
__global__ void k_lse_apply(float* __restrict__ logits) {
    int i = blockIdx.x * blockDim.x + threadIdx.x;
    if (i < V) logits[i] -= g_logZ;
}

// =================================================================================
extern "C" void kernel_launch(void* const* d_in, const int* in_sizes, int n_in,
                              void* d_out, int out_size) {
    const long long* input_ids = (const long long*)d_in[0];
    const float* hidden  = (const float*)d_in[1];   // (2,1,H)
    const float* enc     = (const float*)d_in[2];   // (L,H)
    const float* emb     = (const float*)d_in[3];   // (V,H)
    const float* attn_w  = (const float*)d_in[4];   // (L,2H)
    const float* attn_b  = (const float*)d_in[5];
    const float* comb_w  = (const float*)d_in[6];   // (H,2H)
    const float* comb_b  = (const float*)d_in[7];
    const float* w_ih0   = (const float*)d_in[8];
    const float* w_hh0   = (const float*)d_in[9];
    const float* b_ih0   = (const float*)d_in[10];
    const float* b_hh0   = (const float*)d_in[11];
    const float* w_ih1   = (const float*)d_in[12];
    const float* w_hh1   = (const float*)d_in[13];
    const float* b_ih1   = (const float*)d_in[14];
    const float* b_hh1   = (const float*)d_in[15];
    const float* out_w   = (const float*)d_in[16];  // (V,H)
    const float* out_b   = (const float*)d_in[17];

    float* out = (float*)d_out;
    // layout: [0,V) log_softmax, [V, V+2H) new_hidden, [V+2H, V+2H+L) attn_weights

    const float* h0_prev = hidden;
    const float* h1_prev = hidden + H;

    float* p_h0;  cudaGetSymbolAddress((void**)&p_h0, g_h0);
    float* p_h1;  cudaGetSymbolAddress((void**)&p_h1, g_h1);
    float* p_x;   cudaGetSymbolAddress((void**)&p_x, g_x);

    // attention
    k_attn_logits<<<L, 256>>>(input_ids, emb, h0_prev, attn_w, attn_b);
    k_attn_softmax<<<1, L>>>(out);
    k_attn_applied<<<H / 128, 128>>>(enc);

    // combine + relu
    k_comb<<<H, 256>>>(input_ids, emb, comb_w, comb_b);

    // GRU layer 0
    k_gru_gates<<<3 * H, 256>>>(p_x, h0_prev, w_ih0, w_hh0, b_ih0, b_hh0);
    k_gru_combine<<<1, H>>>(h0_prev, p_h0, out + V);

    // GRU layer 1
    k_gru_gates<<<3 * H, 256>>>(p_h0, h1_prev, w_ih1, w_hh1, b_ih1, b_hh1);
    k_gru_combine<<<1, H>>>(h1_prev, p_h1, out + V + H);

    // output projection + log_softmax
    k_logits<<<(V + 7) / 8, 256>>>(out_w, out_b, out);
    k_lse_partial<<<RED_BLOCKS, 256>>>(out);
    k_lse_final<<<1, RED_BLOCKS>>>();
    k_lse_apply<<<(V + 255) / 256, 256>>>(out);
}